// round 5
// baseline (speedup 1.0000x reference)
#include <cuda_runtime.h>

#define N_NODES 50000
#define EDGE_F  13
#define HID     32
#define NB      8            // nodes per main edge-block (deg<=32 -> <=256 edges)
#define CHE     256          // edges per chunk (single chunk for main blocks)
#define PAIRS   128          // CHE/2
#define EX      64           // dedicated blocks for node 0
#define NBLK    ((N_NODES + NB - 1) / NB)   // 6250
#define SCAN_B  512
#define SCAN_NB ((N_NODES + SCAN_B - 1) / SCAN_B)   // 98

typedef unsigned long long ull;

// node-0 partials (written unconditionally by EX blocks; no zeroing needed)
__device__ ull   Mg0x[EX][256];
__device__ float Sg0x[EX][16];
// prefix-sum of degs
__device__ int   StartsG[N_NODES];
__device__ int   PsumG[128];
__device__ int   OffG[128];

// ---- packed fp32x2 helpers (sm_103a FFMA2, PTX-only) ----
__device__ __forceinline__ ull pk2(float a, float b) {
    ull r; asm("mov.b64 %0, {%1,%2};" : "=l"(r) : "f"(a), "f"(b)); return r;
}
__device__ __forceinline__ ull ffma2(ull a, ull b, ull c) {
    ull d; asm("fma.rn.f32x2 %0, %1, %2, %3;" : "=l"(d) : "l"(a), "l"(b), "l"(c)); return d;
}
__device__ __forceinline__ ull add2(ull a, ull b) {
    ull d; asm("add.rn.f32x2 %0, %1, %2;" : "=l"(d) : "l"(a), "l"(b)); return d;
}
__device__ __forceinline__ float2 unpk(ull a) {
    float2 f; asm("mov.b64 {%0,%1}, %2;" : "=f"(f.x), "=f"(f.y) : "l"(a)); return f;
}

// ---------------------------------------------------------------------------
// scan: Starts[n] = exclusive prefix sum of (int)degs
// ---------------------------------------------------------------------------
__global__ void scan1_kernel(const float* __restrict__ degs)
{
    __shared__ int s[SCAN_B];
    int b = blockIdx.x, t = threadIdx.x, n = b * SCAN_B + t;
    int d = (n < N_NODES) ? (int)degs[n] : 0;
    s[t] = d;
    for (int off = 1; off < SCAN_B; off <<= 1) {
        __syncthreads();
        int v = (t >= off) ? s[t - off] : 0;
        __syncthreads();
        s[t] += v;
    }
    if (n < N_NODES) StartsG[n] = s[t] - d;     // exclusive
    if (t == SCAN_B - 1) PsumG[b] = s[t];
}

__global__ void scan2_kernel()
{
    __shared__ int s[128];
    int t = threadIdx.x;
    s[t] = (t < SCAN_NB) ? PsumG[t] : 0;
    __syncthreads();
    if (t == 0) {
        int acc = 0;
        for (int i = 0; i < SCAN_NB; i++) { int v = s[i]; s[i] = acc; acc += v; }
    }
    __syncthreads();
    if (t < SCAN_NB) OffG[t] = s[t];
}

// ---------------------------------------------------------------------------
// Fused edge+GEMM kernel.
// ---------------------------------------------------------------------------
struct SmemT {
    ull Xp[16][PAIRS + 1];           // x[src] pairs, transposed
    ull Hp[HID][PAIRS + 1];          // packed {h(2q), h(2q+1)}
    union {
        ull EFp[EDGE_F][PAIRS + 1];  // ef staging (dead after h-compute)
        ull Mbuf[NB][256];           // per-node M (live after)
    } u;
    ull W2c[256][16];                // packed W2 pairs [k=j*8+p][o]
    ull b2q[8][16];
    ull Sb2[NB][8];                  // per-node S as float[16] rows
    ull red[128];                    // GEMM half-reduction
    int sb[12];
};

__global__ void __launch_bounds__(256, 2)
edge_kernel(const float* __restrict__ x,
            const float* __restrict__ ef,
            const float* __restrict__ W1,
            const float* __restrict__ b1,
            const float* __restrict__ W2,
            const float* __restrict__ b2,
            const int*   __restrict__ idxn,
            const float* __restrict__ degs,
            float* __restrict__ out,
            int E)
{
    extern __shared__ char smem_raw[];
    SmemT* SM = (SmemT*)smem_raw;

    const int tid = threadIdx.x;
    const int bx  = blockIdx.x;
    const int j   = tid >> 3;      // M-slot row (0..31)
    const int p   = tid & 7;       // M-slot i-pair
    const int jj  = tid & 31;      // h-compute column

    // W1 column in regs, packed {w,w}
    ull W1r[EDGE_F], b1r;
    #pragma unroll
    for (int f = 0; f < EDGE_F; f++) {
        float w = __ldg(W1 + f * HID + jj);
        W1r[f] = pk2(w, w);
    }
    { float bb = __ldg(b1 + jj); b1r = pk2(bb, bb); }

    const bool is_main = (bx < NBLK);
    float* EFf = (float*)SM->u.EFp;
    float* Xf  = (float*)SM->Xp;
    const ull* hrow = SM->Hp[j];
    const ull* xa   = SM->Xp[2 * p];
    const ull* xb   = SM->Xp[2 * p + 1];

    if (is_main) {
        const int t0 = (bx == 0) ? 1 : bx * NB;
        int t1 = bx * NB + NB; if (t1 > N_NODES) t1 = N_NODES;
        const int nn = t1 - t0;

        // segment bounds from precomputed scan (2 parallel L2 loads, no search)
        if (tid <= NB) {
            int target = t0 + tid; if (target > t1) target = t1;
            SM->sb[tid] = (target >= N_NODES) ? E
                          : (StartsG[target] + OffG[target >> 9]);
        }
        // stage W2 packed pairs + b2 (independent; issue before the barrier)
        for (int t = tid; t < 256 * 16; t += 256) {
            int k = t >> 4, o = t & 15;
            int jw = k >> 3, pw = k & 7;
            SM->W2c[k][o] = pk2(__ldg(W2 + jw * 256 + 2 * pw * 16 + o),
                                __ldg(W2 + jw * 256 + (2 * pw + 1) * 16 + o));
        }
        if (tid < 128) {
            int pp = tid >> 4, o = tid & 15;
            SM->b2q[pp][o] = pk2(__ldg(b2 + 2 * pp * 16 + o),
                                 __ldg(b2 + (2 * pp + 1) * 16 + o));
        }
        __syncthreads();

        const int es = SM->sb[0];
        const int c  = SM->sb[NB] - es;         // <= 256
        const int cpad = (c + 1) & ~1;
        const int qn = cpad >> 1;

        // ---- stage ef ----
        for (int k = tid; k < cpad * EDGE_F; k += 256) {
            int e = k / EDGE_F, f = k - e * EDGE_F;
            EFf[f * 2 * (PAIRS + 1) + e] =
                (e < c) ? __ldg(ef + (size_t)es * EDGE_F + k) : 0.f;
        }
        // ---- stage x[src] (gather) ----
        for (int t = tid; t < cpad * 4; t += 256) {
            int e = t >> 2, r = t & 3;
            float4 v = make_float4(0.f, 0.f, 0.f, 0.f);
            if (e < c) {
                int src = __ldg(idxn + es + e);
                v = __ldg((const float4*)x + (size_t)src * 4 + r);
            }
            Xf[(r * 4 + 0) * 2 * (PAIRS + 1) + e] = v.x;
            Xf[(r * 4 + 1) * 2 * (PAIRS + 1) + e] = v.y;
            Xf[(r * 4 + 2) * 2 * (PAIRS + 1) + e] = v.z;
            Xf[(r * 4 + 3) * 2 * (PAIRS + 1) + e] = v.w;
        }
        __syncthreads();

        // ---- h pairs ----
        for (int t = tid; t < (qn << 5); t += 256) {
            int q = t >> 5;
            ull h2 = b1r;
            #pragma unroll
            for (int f = 0; f < EDGE_F; f++)
                h2 = ffma2(SM->u.EFp[f][q], W1r[f], h2);
            float2 hf = unpk(h2);
            SM->Hp[jj][q] = pk2(fmaxf(hf.x, 0.f), fmaxf(hf.y, 0.f));
        }
        __syncthreads();   // EFp dead -> Mbuf alias live

        // ---- per-node masked rank-1 accumulation, flush to smem ----
        #pragma unroll 1
        for (int k = 0; k < NB; k++) {
            const int aL = SM->sb[k] - es;
            const int bL = SM->sb[k + 1] - es;
            ull a0 = 0ull, a1 = 0ull, aS = 0ull;
            if (bL > aL) {
                const int qs = aL >> 1, qe = (bL - 1) >> 1;
                const ull mlo = (aL & 1) ? 0xFFFFFFFF00000000ull : ~0ull;
                const ull mhi = (bL & 1) ? 0x00000000FFFFFFFFull : ~0ull;
                ull h2 = hrow[qs] & mlo;
                if (qe == qs) h2 &= mhi;
                a0 = ffma2(h2, xa[qs], a0);
                a1 = ffma2(h2, xb[qs], a1);
                #pragma unroll 2
                for (int q = qs + 1; q < qe; q++) {
                    h2 = hrow[q];
                    a0 = ffma2(h2, xa[q], a0);
                    a1 = ffma2(h2, xb[q], a1);
                }
                if (qe > qs) {
                    h2 = hrow[qe] & mhi;
                    a0 = ffma2(h2, xa[qe], a0);
                    a1 = ffma2(h2, xb[qe], a1);
                }
                if (tid < 16) {
                    const ull* xr = SM->Xp[tid];
                    ull x2 = xr[qs] & mlo;
                    if (qe == qs) x2 &= mhi;
                    aS = add2(aS, x2);
                    for (int q = qs + 1; q < qe; q++) aS = add2(aS, xr[q]);
                    if (qe > qs) aS = add2(aS, xr[qe] & mhi);
                }
            }
            // unconditional flush (zeros for empty/deg-0 nodes)
            float2 fa = unpk(a0), fb = unpk(a1);
            SM->u.Mbuf[k][tid] = pk2(fa.x + fa.y, fb.x + fb.y);
            if (tid < 16) {
                float2 fs = unpk(aS);
                ((float*)SM->Sb2)[k * 16 + tid] = fs.x + fs.y;
            }
        }
        __syncthreads();

        // ---- in-block GEMM: out[g,o] = M[g,:] . W2c[:,o] (+ S.b2) / deg ----
        const int half = tid >> 7;
        const int g = (tid >> 4) & 7;
        const int o = tid & 15;
        const ull* mrow = SM->u.Mbuf[g];
        const int k0 = half * 128;
        ull s = 0ull;
        #pragma unroll 8
        for (int kk = 0; kk < 128; kk++)
            s = ffma2(mrow[k0 + kk], SM->W2c[k0 + kk][o], s);
        if (half) SM->red[g * 16 + o] = s;
        __syncthreads();
        if (!half) {
            s = add2(s, SM->red[g * 16 + o]);
            const ull* sb2 = SM->Sb2[g];
            #pragma unroll
            for (int pp = 0; pp < 8; pp++)
                s = ffma2(sb2[pp], SM->b2q[pp][o], s);
            if (g < nn) {
                float2 f = unpk(s);
                float d = __ldg(degs + t0 + g);
                out[(t0 + g) * 16 + o] = (d > 0.f) ? (f.x + f.y) / d : 0.f;
            }
        }
    } else {
        // ---- node-0 partial blocks ----
        const int ex = bx - NBLK;
        const int e0e = (int)__ldg(degs);       // node 0's edges = [0, degs[0])
        ull accA = 0ull, accB = 0ull, accS = 0ull;

        for (int base = ex * CHE; base < e0e; base += EX * CHE) {
            const int c = min(CHE, e0e - base);
            const int cpad = (c + 1) & ~1;
            const int qn = cpad >> 1;

            for (int k = tid; k < cpad * EDGE_F; k += 256) {
                int e = k / EDGE_F, f = k - e * EDGE_F;
                EFf[f * 2 * (PAIRS + 1) + e] =
                    (e < c) ? __ldg(ef + (size_t)base * EDGE_F + k) : 0.f;
            }
            for (int t = tid; t < cpad * 4; t += 256) {
                int e = t >> 2, r = t & 3;
                float4 v = make_float4(0.f, 0.f, 0.f, 0.f);
                if (e < c) {
                    int src = __ldg(idxn + base + e);
                    v = __ldg((const float4*)x + (size_t)src * 4 + r);
                }
                Xf[(r * 4 + 0) * 2 * (PAIRS + 1) + e] = v.x;
                Xf[(r * 4 + 1) * 2 * (PAIRS + 1) + e] = v.y;
                Xf[(r * 4 + 2) * 2 * (PAIRS + 1) + e] = v.z;
                Xf[(r * 4 + 3) * 2 * (PAIRS + 1) + e] = v.w;
            }
            __syncthreads();

            for (int t = tid; t < (qn << 5); t += 256) {
                int q = t >> 5;
                ull h2 = b1r;
                #pragma unroll
                for (int f = 0; f < EDGE_F; f++)
                    h2 = ffma2(SM->u.EFp[f][q], W1r[f], h2);
                float2 hf = unpk(h2);
                SM->Hp[jj][q] = pk2(fmaxf(hf.x, 0.f), fmaxf(hf.y, 0.f));
            }
            __syncthreads();

            #pragma unroll 2
            for (int q = 0; q < qn; q++) {       // pad edges have x=0
                ull h2 = hrow[q];
                accA = ffma2(h2, xa[q], accA);
                accB = ffma2(h2, xb[q], accB);
            }
            if (tid < 16) {
                const ull* xr = SM->Xp[tid];
                for (int q = 0; q < qn; q++) accS = add2(accS, xr[q]);
            }
            __syncthreads();
        }
        float2 fa = unpk(accA), fb = unpk(accB);
        Mg0x[ex][tid] = pk2(fa.x + fa.y, fb.x + fb.y);
        if (tid < 16) {
            float2 fs = unpk(accS);
            Sg0x[ex][tid] = fs.x + fs.y;
        }
    }
}

// ---------------------------------------------------------------------------
// node 0 finalize: reduce EX partial rows, contract with W2, write out[0,:]
// ---------------------------------------------------------------------------
__global__ void __launch_bounds__(256)
node0_kernel(const float* __restrict__ W2,
             const float* __restrict__ b2,
             const float* __restrict__ degs,
             float* __restrict__ out)
{
    __shared__ float wred[8][16];
    __shared__ float ssum[16];
    int tid = threadIdx.x, lane = tid & 31, w = tid >> 5;

    ull m = 0ull;
    #pragma unroll 8
    for (int ex = 0; ex < EX; ex++) m = add2(m, Mg0x[ex][tid]);
    if (tid < 16) {
        float s = 0.f;
        for (int ex = 0; ex < EX; ex++) s += Sg0x[ex][tid];
        ssum[tid] = s;
    }
    int jn = tid >> 3, pn = tid & 7;
    float2 f = unpk(m);
    float po[16];
    #pragma unroll
    for (int o = 0; o < 16; o++)
        po[o] = f.x * __ldg(W2 + jn * 256 + 2 * pn * 16 + o)
              + f.y * __ldg(W2 + jn * 256 + (2 * pn + 1) * 16 + o);
    #pragma unroll
    for (int o = 0; o < 16; o++)
        #pragma unroll
        for (int off = 16; off; off >>= 1)
            po[o] += __shfl_down_sync(0xffffffffu, po[o], off);
    if (lane == 0)
        #pragma unroll
        for (int o = 0; o < 16; o++) wred[w][o] = po[o];
    __syncthreads();
    if (tid < 16) {
        float t = 0.f;
        #pragma unroll
        for (int w2 = 0; w2 < 8; w2++) t += wred[w2][tid];
        float s2 = 0.f;
        #pragma unroll
        for (int i = 0; i < 16; i++) s2 += ssum[i] * __ldg(b2 + i * 16 + tid);
        float d = __ldg(degs);
        out[tid] = (d > 0.f) ? (t + s2) / d : 0.f;
    }
}

// ---------------------------------------------------------------------------
extern "C" void kernel_launch(void* const* d_in, const int* in_sizes, int n_in,
                              void* d_out, int out_size)
{
    const float* x    = (const float*)d_in[0];
    const float* ef   = (const float*)d_in[1];
    const float* W1   = (const float*)d_in[2];
    const float* b1   = (const float*)d_in[3];
    const float* W2   = (const float*)d_in[4];
    const float* b2   = (const float*)d_in[5];
    const int*   idxn = (const int*)d_in[6];
    const float* degs = (const float*)d_in[8];
    float* out = (float*)d_out;

    const int E = in_sizes[6];
    static int smem_set = 0;
    if (!smem_set) {
        cudaFuncSetAttribute(edge_kernel,
                             cudaFuncAttributeMaxDynamicSharedMemorySize,
                             (int)sizeof(SmemT));
        smem_set = 1;
    }

    scan1_kernel<<<SCAN_NB, SCAN_B>>>(degs);
    scan2_kernel<<<1, 128>>>();
    edge_kernel<<<NBLK + EX, 256, sizeof(SmemT)>>>(x, ef, W1, b1, W2, b2,
                                                   idxn, degs, out, E);
    node0_kernel<<<1, 256>>>(W2, b2, degs, out);
}

// round 6
// speedup vs baseline: 1.1876x; 1.1876x over previous
#include <cuda_runtime.h>

#define N_NODES 50000
#define EDGE_F  13
#define HID     32
#define NB      8            // nodes per main block (deg<=32 -> <=256 edges)
#define CH      128          // edges per staging chunk (<=2 chunks per block)
#define PAIRS   64           // CH/2
#define EX      16           // node-0 slice blocks (placed first in grid)
#define NBLK    ((N_NODES + NB - 1) / NB)   // 6250
#define SCAN_B  512
#define SCAN_NB ((N_NODES + SCAN_B - 1) / SCAN_B)   // 98

typedef unsigned long long ull;

__device__ ull   W2P[256][16];     // packed W2 pairs [k=j*8+p][o] (4 KB, L1-hot)
__device__ ull   b2P[8][16];
__device__ ull   Mg0x[EX][256];    // node-0 partials
__device__ float Sg0x[EX][16];
__device__ int   StartsG[N_NODES];
__device__ int   PsumG[128];
__device__ int   OffG[128];

// ---- packed fp32x2 helpers (sm_103a FFMA2, PTX-only) ----
__device__ __forceinline__ ull pk2(float a, float b) {
    ull r; asm("mov.b64 %0, {%1,%2};" : "=l"(r) : "f"(a), "f"(b)); return r;
}
__device__ __forceinline__ ull ffma2(ull a, ull b, ull c) {
    ull d; asm("fma.rn.f32x2 %0, %1, %2, %3;" : "=l"(d) : "l"(a), "l"(b), "l"(c)); return d;
}
__device__ __forceinline__ ull add2(ull a, ull b) {
    ull d; asm("add.rn.f32x2 %0, %1, %2;" : "=l"(d) : "l"(a), "l"(b)); return d;
}
__device__ __forceinline__ float2 unpk(ull a) {
    float2 f; asm("mov.b64 {%0,%1}, %2;" : "=f"(f.x), "=f"(f.y) : "l"(a)); return f;
}

// ---------------------------------------------------------------------------
__global__ void pack_kernel(const float* __restrict__ W2, const float* __restrict__ b2)
{
    int tid = threadIdx.x;
    for (int t = tid; t < 256 * 16; t += 256) {
        int k = t >> 4, o = t & 15;
        int jw = k >> 3, pw = k & 7;
        W2P[k][o] = pk2(__ldg(W2 + jw * 256 + 2 * pw * 16 + o),
                        __ldg(W2 + jw * 256 + (2 * pw + 1) * 16 + o));
    }
    if (tid < 128) {
        int pp = tid >> 4, o = tid & 15;
        b2P[pp][o] = pk2(__ldg(b2 + 2 * pp * 16 + o),
                         __ldg(b2 + (2 * pp + 1) * 16 + o));
    }
}

__global__ void scan1_kernel(const float* __restrict__ degs)
{
    __shared__ int s[SCAN_B];
    int b = blockIdx.x, t = threadIdx.x, n = b * SCAN_B + t;
    int d = (n < N_NODES) ? (int)degs[n] : 0;
    s[t] = d;
    for (int off = 1; off < SCAN_B; off <<= 1) {
        __syncthreads();
        int v = (t >= off) ? s[t - off] : 0;
        __syncthreads();
        s[t] += v;
    }
    if (n < N_NODES) StartsG[n] = s[t] - d;     // exclusive
    if (t == SCAN_B - 1) PsumG[b] = s[t];
}

__global__ void scan2_kernel()
{
    __shared__ int s[128];
    int t = threadIdx.x;
    s[t] = (t < SCAN_NB) ? PsumG[t] : 0;
    __syncthreads();
    if (t == 0) {
        int acc = 0;
        for (int i = 0; i < SCAN_NB; i++) { int v = s[i]; s[i] = acc; acc += v; }
    }
    __syncthreads();
    if (t < SCAN_NB) OffG[t] = s[t];
}

// ---------------------------------------------------------------------------
struct SmemT {
    ull EFp[EDGE_F][PAIRS + 1];   // 6.8 KB
    ull Xp[16][PAIRS + 1];        // 8.3 KB
    ull Hp[HID][PAIRS + 1];       // 16.6 KB
    ull W1s[EDGE_F][HID];         // 3.3 KB packed {w,w}
    ull b1s[HID];
    ull Mbuf[NB][258];            // 16.5 KB (row pad -> distinct banks)
    ull Sb2[NB][8];               // float[8][16] view
    ull red[128];
    int sb[NB + 4];
};                                // ~53.4 KB -> 4 blocks/SM

__global__ void __launch_bounds__(256, 4)
fused_kernel(const float* __restrict__ x,
             const float* __restrict__ ef,
             const float* __restrict__ W1,
             const float* __restrict__ b1,
             const int*   __restrict__ idxn,
             const float* __restrict__ degs,
             float* __restrict__ out,
             int E)
{
    extern __shared__ char smem_raw[];
    SmemT* SM = (SmemT*)smem_raw;
    const int tid = threadIdx.x;
    const int bx  = blockIdx.x;
    const int j = tid >> 3, p = tid & 7;

    // stage packed W1 + b1 (smem, frees 26 regs vs register-resident)
    for (int t = tid; t < EDGE_F * HID; t += 256) {
        float w = __ldg(W1 + t);
        SM->W1s[t / HID][t % HID] = pk2(w, w);
    }
    if (tid < HID) { float bb = __ldg(b1 + tid); SM->b1s[tid] = pk2(bb, bb); }

    float* EFf = (float*)SM->EFp;
    float* Xf  = (float*)SM->Xp;
    const ull* hrow = SM->Hp[j];
    const ull* xa   = SM->Xp[2 * p];
    const ull* xb   = SM->Xp[2 * p + 1];
    const ull* w2p  = &W2P[0][0];

    if (bx >= EX) {
        // ================= main blocks: 8 nodes, <=2 chunks =================
        const int mb = bx - EX;
        const int t0 = (mb == 0) ? 1 : mb * NB;     // node 0 excluded
        int t1 = mb * NB + NB; if (t1 > N_NODES) t1 = N_NODES;
        const int nn = t1 - t0;

        if (tid <= NB) {
            int target = t0 + tid; if (target > t1) target = t1;
            SM->sb[tid] = (target >= N_NODES) ? E
                          : (StartsG[target] + OffG[target >> 9]);
        }
        __syncthreads();

        const int es = SM->sb[0];
        const int ee = SM->sb[NB];
        ull a0 = 0ull, a1 = 0ull, aS = 0ull;

        for (int base = es; base < ee; base += CH) {
            const int c = min(CH, ee - base);
            const int cpad = (c + 1) & ~1;
            const int qn = cpad >> 1;

            for (int k = tid; k < cpad * EDGE_F; k += 256) {
                int e = k / EDGE_F, f = k - e * EDGE_F;
                EFf[f * 130 + e] = (e < c) ? __ldg(ef + (size_t)base * EDGE_F + k) : 0.f;
            }
            for (int t = tid; t < cpad * 4; t += 256) {
                int e = t >> 2, r = t & 3;
                float4 v = make_float4(0.f, 0.f, 0.f, 0.f);
                if (e < c) {
                    int src = __ldg(idxn + base + e);
                    v = __ldg((const float4*)x + (size_t)src * 4 + r);
                }
                Xf[(r * 4 + 0) * 130 + e] = v.x;
                Xf[(r * 4 + 1) * 130 + e] = v.y;
                Xf[(r * 4 + 2) * 130 + e] = v.z;
                Xf[(r * 4 + 3) * 130 + e] = v.w;
            }
            __syncthreads();

            for (int t = tid; t < (qn << 5); t += 256) {
                int q = t >> 5, jj = t & 31;
                ull h2 = SM->b1s[jj];
                #pragma unroll
                for (int f = 0; f < EDGE_F; f++)
                    h2 = ffma2(SM->EFp[f][q], SM->W1s[f][jj], h2);
                float2 hf = unpk(h2);
                SM->Hp[jj][q] = pk2(fmaxf(hf.x, 0.f), fmaxf(hf.y, 0.f));
            }
            __syncthreads();

            const int cend = base + c;
            #pragma unroll 1
            for (int k = 0; k < NB; k++) {
                const int ak = SM->sb[k], bk = SM->sb[k + 1];
                int aL = ak - base; if (aL < 0) aL = 0;
                int bL = bk - base; if (bL > c) bL = c;
                if (bL > aL) {
                    const int qs = aL >> 1, qe = (bL - 1) >> 1;
                    const ull mlo = (aL & 1) ? 0xFFFFFFFF00000000ull : ~0ull;
                    const ull mhi = (bL & 1) ? 0x00000000FFFFFFFFull : ~0ull;
                    ull h2 = hrow[qs] & mlo;
                    if (qe == qs) h2 &= mhi;
                    a0 = ffma2(h2, xa[qs], a0);
                    a1 = ffma2(h2, xb[qs], a1);
                    #pragma unroll 2
                    for (int q = qs + 1; q < qe; q++) {
                        h2 = hrow[q];
                        a0 = ffma2(h2, xa[q], a0);
                        a1 = ffma2(h2, xb[q], a1);
                    }
                    if (qe > qs) {
                        h2 = hrow[qe] & mhi;
                        a0 = ffma2(h2, xa[qe], a0);
                        a1 = ffma2(h2, xb[qe], a1);
                    }
                    if (tid < 16) {
                        const ull* xr = SM->Xp[tid];
                        ull x2 = xr[qs] & mlo;
                        if (qe == qs) x2 &= mhi;
                        aS = add2(aS, x2);
                        for (int q = qs + 1; q < qe; q++) aS = add2(aS, xr[q]);
                        if (qe > qs) aS = add2(aS, xr[qe] & mhi);
                    }
                }
                // flush iff this node's segment ENDS in this chunk
                if (bk > base && bk <= cend && bk > ak) {
                    float2 fa = unpk(a0), fb = unpk(a1);
                    SM->Mbuf[k][tid] = pk2(fa.x + fa.y, fb.x + fb.y);
                    a0 = 0ull; a1 = 0ull;
                    if (tid < 16) {
                        float2 fs = unpk(aS);
                        ((float*)SM->Sb2)[k * 16 + tid] = fs.x + fs.y;
                        aS = 0ull;
                    }
                }
            }
            __syncthreads();   // protect Hp/Xp before re-staging
        }

        // ---- in-block GEMM: W2 via L1-resident global (no per-block staging) ----
        const int half = tid >> 7;
        const int g = (tid >> 4) & 7;
        const int o = tid & 15;
        const ull* mrow = SM->Mbuf[g];
        const int k0 = half << 7;
        ull s = 0ull;
        #pragma unroll 8
        for (int kk = 0; kk < 128; kk++)
            s = ffma2(mrow[k0 + kk], __ldg(w2p + (size_t)(k0 + kk) * 16 + o), s);
        if (half) SM->red[g * 16 + o] = s;
        __syncthreads();
        if (!half) {
            s = add2(s, SM->red[g * 16 + o]);
            #pragma unroll
            for (int pp = 0; pp < 8; pp++)
                s = ffma2(SM->Sb2[g][pp], __ldg(&b2P[0][0] + pp * 16 + o), s);
            if (g < nn) {
                float2 f = unpk(s);
                float d = __ldg(degs + t0 + g);
                out[(t0 + g) * 16 + o] = (d > 0.f) ? (f.x + f.y) / d : 0.f;
            }
        }
    } else {
        // ================= node-0 slice blocks =================
        const int e0e = (int)__ldg(degs);   // node 0 owns edges [0, degs[0])
        ull a0 = 0ull, a1 = 0ull, aS = 0ull;
        __syncthreads();                    // W1s/b1s ready

        for (int base = bx * CH; base < e0e; base += EX * CH) {
            const int c = min(CH, e0e - base);
            const int cpad = (c + 1) & ~1;
            const int qn = cpad >> 1;

            for (int k = tid; k < cpad * EDGE_F; k += 256) {
                int e = k / EDGE_F, f = k - e * EDGE_F;
                EFf[f * 130 + e] = (e < c) ? __ldg(ef + (size_t)base * EDGE_F + k) : 0.f;
            }
            for (int t = tid; t < cpad * 4; t += 256) {
                int e = t >> 2, r = t & 3;
                float4 v = make_float4(0.f, 0.f, 0.f, 0.f);
                if (e < c) {
                    int src = __ldg(idxn + base + e);
                    v = __ldg((const float4*)x + (size_t)src * 4 + r);
                }
                Xf[(r * 4 + 0) * 130 + e] = v.x;
                Xf[(r * 4 + 1) * 130 + e] = v.y;
                Xf[(r * 4 + 2) * 130 + e] = v.z;
                Xf[(r * 4 + 3) * 130 + e] = v.w;
            }
            __syncthreads();

            for (int t = tid; t < (qn << 5); t += 256) {
                int q = t >> 5, jj = t & 31;
                ull h2 = SM->b1s[jj];
                #pragma unroll
                for (int f = 0; f < EDGE_F; f++)
                    h2 = ffma2(SM->EFp[f][q], SM->W1s[f][jj], h2);
                float2 hf = unpk(h2);
                SM->Hp[jj][q] = pk2(fmaxf(hf.x, 0.f), fmaxf(hf.y, 0.f));
            }
            __syncthreads();

            #pragma unroll 2
            for (int q = 0; q < qn; q++) {     // pad edges have x = 0
                ull h2 = hrow[q];
                a0 = ffma2(h2, xa[q], a0);
                a1 = ffma2(h2, xb[q], a1);
            }
            if (tid < 16) {
                const ull* xr = SM->Xp[tid];
                for (int q = 0; q < qn; q++) aS = add2(aS, xr[q]);
            }
            __syncthreads();
        }
        float2 fa = unpk(a0), fb = unpk(a1);
        Mg0x[bx][tid] = pk2(fa.x + fa.y, fb.x + fb.y);
        if (tid < 16) {
            float2 fs = unpk(aS);
            Sg0x[bx][tid] = fs.x + fs.y;
        }
    }
}

// ---------------------------------------------------------------------------
__global__ void __launch_bounds__(256)
node0_kernel(const float* __restrict__ degs, float* __restrict__ out)
{
    __shared__ float wred[8][16];
    __shared__ float ssum[16];
    int tid = threadIdx.x, lane = tid & 31, w = tid >> 5;

    ull m = Mg0x[0][tid];
    #pragma unroll
    for (int e2 = 1; e2 < EX; e2++) m = add2(m, Mg0x[e2][tid]);
    if (tid < 16) {
        float s = 0.f;
        #pragma unroll
        for (int e2 = 0; e2 < EX; e2++) s += Sg0x[e2][tid];
        ssum[tid] = s;
    }
    float po[16];
    #pragma unroll
    for (int o = 0; o < 16; o++) {
        ull t2 = ffma2(m, W2P[tid][o], 0ull);
        float2 f = unpk(t2);
        po[o] = f.x + f.y;
    }
    #pragma unroll
    for (int o = 0; o < 16; o++)
        #pragma unroll
        for (int off = 16; off; off >>= 1)
            po[o] += __shfl_down_sync(0xffffffffu, po[o], off);
    if (lane == 0)
        #pragma unroll
        for (int o = 0; o < 16; o++) wred[w][o] = po[o];
    __syncthreads();
    if (tid < 16) {
        float t = 0.f;
        #pragma unroll
        for (int w2 = 0; w2 < 8; w2++) t += wred[w2][tid];
        float s2 = 0.f;
        #pragma unroll
        for (int pp = 0; pp < 8; pp++) {
            ull q = ffma2(pk2(ssum[2 * pp], ssum[2 * pp + 1]), b2P[pp][tid], 0ull);
            float2 f = unpk(q);
            s2 += f.x + f.y;
        }
        float d = __ldg(degs);
        out[tid] = (d > 0.f) ? (t + s2) / d : 0.f;
    }
}

// ---------------------------------------------------------------------------
extern "C" void kernel_launch(void* const* d_in, const int* in_sizes, int n_in,
                              void* d_out, int out_size)
{
    const float* x    = (const float*)d_in[0];
    const float* ef   = (const float*)d_in[1];
    const float* W1   = (const float*)d_in[2];
    const float* b1   = (const float*)d_in[3];
    const float* W2   = (const float*)d_in[4];
    const float* b2   = (const float*)d_in[5];
    const int*   idxn = (const int*)d_in[6];
    const float* degs = (const float*)d_in[8];
    float* out = (float*)d_out;

    const int E = in_sizes[6];
    static int smem_set = 0;
    if (!smem_set) {
        cudaFuncSetAttribute(fused_kernel,
                             cudaFuncAttributeMaxDynamicSharedMemorySize,
                             (int)sizeof(SmemT));
        smem_set = 1;
    }

    pack_kernel<<<1, 256>>>(W2, b2);
    scan1_kernel<<<SCAN_NB, SCAN_B>>>(degs);
    scan2_kernel<<<1, 128>>>();
    fused_kernel<<<EX + NBLK, 256, sizeof(SmemT)>>>(x, ef, W1, b1, idxn, degs, out, E);
    node0_kernel<<<1, 256>>>(degs, out);
}

// round 7
// speedup vs baseline: 1.2248x; 1.0313x over previous
#include <cuda_runtime.h>

#define N_NODES 50000
#define EDGE_F  13
#define HID     32
#define NB      8            // nodes per main block (deg<=32 -> <=256 edges)
#define CH      128          // edges per staging chunk
#define PAIRS   64           // CH/2
#define EX      16           // node-0 slice blocks (first in grid)
#define NBLK    ((N_NODES + NB - 1) / NB)   // 6250
#define SCAN_B  512
#define SCAN_NB ((N_NODES + SCAN_B - 1) / SCAN_B)   // 98

typedef unsigned long long ull;

__device__ ulonglong2 W2Q[128][16];   // k-paired packed W2 (8 KB, L1-hot)
__device__ ull        b2P[8][16];
__device__ ull        Mg0x[EX][256];
__device__ float      Sg0x[EX][16];
__device__ int        StartsG[N_NODES];
__device__ int        PsumG[128];
__device__ int        OffG[128];

// ---- packed fp32x2 helpers (sm_103a FFMA2, PTX-only) ----
__device__ __forceinline__ ull pk2(float a, float b) {
    ull r; asm("mov.b64 %0, {%1,%2};" : "=l"(r) : "f"(a), "f"(b)); return r;
}
__device__ __forceinline__ ull ffma2(ull a, ull b, ull c) {
    ull d; asm("fma.rn.f32x2 %0, %1, %2, %3;" : "=l"(d) : "l"(a), "l"(b), "l"(c)); return d;
}
__device__ __forceinline__ ull add2(ull a, ull b) {
    ull d; asm("add.rn.f32x2 %0, %1, %2;" : "=l"(d) : "l"(a), "l"(b)); return d;
}
__device__ __forceinline__ float2 unpk(ull a) {
    float2 f; asm("mov.b64 {%0,%1}, %2;" : "=f"(f.x), "=f"(f.y) : "l"(a)); return f;
}

// ---------------------------------------------------------------------------
__global__ void pack_kernel(const float* __restrict__ W2, const float* __restrict__ b2)
{
    int tid = threadIdx.x;
    for (int t = tid; t < 128 * 16; t += 256) {
        int k2 = t >> 4, o = t & 15;
        int k0 = 2 * k2, k1 = 2 * k2 + 1;
        int j0 = k0 >> 3, p0 = k0 & 7;
        int j1 = k1 >> 3, p1 = k1 & 7;
        ulonglong2 v;
        v.x = pk2(__ldg(W2 + j0 * 256 + 2 * p0 * 16 + o),
                  __ldg(W2 + j0 * 256 + (2 * p0 + 1) * 16 + o));
        v.y = pk2(__ldg(W2 + j1 * 256 + 2 * p1 * 16 + o),
                  __ldg(W2 + j1 * 256 + (2 * p1 + 1) * 16 + o));
        W2Q[k2][o] = v;
    }
    if (tid < 128) {
        int pp = tid >> 4, o = tid & 15;
        b2P[pp][o] = pk2(__ldg(b2 + 2 * pp * 16 + o),
                         __ldg(b2 + (2 * pp + 1) * 16 + o));
    }
}

__global__ void scan1_kernel(const float* __restrict__ degs)
{
    __shared__ int s[SCAN_B];
    int b = blockIdx.x, t = threadIdx.x, n = b * SCAN_B + t;
    int d = (n < N_NODES) ? (int)degs[n] : 0;
    s[t] = d;
    for (int off = 1; off < SCAN_B; off <<= 1) {
        __syncthreads();
        int v = (t >= off) ? s[t - off] : 0;
        __syncthreads();
        s[t] += v;
    }
    if (n < N_NODES) StartsG[n] = s[t] - d;     // exclusive
    if (t == SCAN_B - 1) PsumG[b] = s[t];
}

__global__ void scan2_kernel()
{
    __shared__ int s[128];
    int t = threadIdx.x;
    s[t] = (t < SCAN_NB) ? PsumG[t] : 0;
    __syncthreads();
    if (t == 0) {
        int acc = 0;
        for (int i = 0; i < SCAN_NB; i++) { int v = s[i]; s[i] = acc; acc += v; }
    }
    __syncthreads();
    if (t < SCAN_NB) OffG[t] = s[t];
}

// ---------------------------------------------------------------------------
struct SmemT {
    ulonglong2 Xq[PAIRS][8];      // 8.0 KB  x pairs, slot = p ^ (q&7)
    ull Mbuf[NB][260];            // 16.6 KB (16B-aligned rows, padded)
    ull Hp[HID][PAIRS + 1];       // 16.6 KB packed {h(2q), h(2q+1)}
    ull EFp[EDGE_F][PAIRS + 1];   // 6.8 KB
    ull W1s[EDGE_F][HID];         // 3.3 KB packed {w,w}
    ull b1s[HID];
    ull Sb2[NB][8];
    ull red[128];
    int sb[NB + 4];
};                                // ~53.4 KB -> 4 blocks/SM

__global__ void __launch_bounds__(256, 4)
fused_kernel(const float* __restrict__ x,
             const float* __restrict__ ef,
             const float* __restrict__ W1,
             const float* __restrict__ b1,
             const int*   __restrict__ idxn,
             const float* __restrict__ degs,
             float* __restrict__ out,
             int E)
{
    extern __shared__ char smem_raw[];
    SmemT* SM = (SmemT*)smem_raw;
    const int tid = threadIdx.x;
    const int bx  = blockIdx.x;
    const int j = tid >> 3, p = tid & 7;

    for (int t = tid; t < EDGE_F * HID; t += 256) {
        float w = __ldg(W1 + t);
        SM->W1s[t / HID][t % HID] = pk2(w, w);
    }
    if (tid < HID) { float bb = __ldg(b1 + tid); SM->b1s[tid] = pk2(bb, bb); }

    float* EFf = (float*)SM->EFp;
    const ull* hrow = SM->Hp[j];

    if (bx >= EX) {
        // ================= main blocks: 8 nodes =================
        const int mb = bx - EX;
        const int t0 = (mb == 0) ? 1 : mb * NB;     // node 0 excluded
        int t1 = mb * NB + NB; if (t1 > N_NODES) t1 = N_NODES;
        const int nn = t1 - t0;

        if (tid <= NB) {
            int target = t0 + tid; if (target > t1) target = t1;
            SM->sb[tid] = (target >= N_NODES) ? E
                          : (StartsG[target] + OffG[target >> 9]);
        }
        __syncthreads();

        const int es = SM->sb[0];
        const int ee = SM->sb[NB];
        ull a0 = 0ull, a1 = 0ull, aS = 0ull;

        for (int base = es; base < ee; base += CH) {
            const int c = min(CH, ee - base);
            const int cpad = (c + 1) & ~1;

            // ---- stage ef (zero-padded to cpad) ----
            for (int k = tid; k < cpad * EDGE_F; k += 256) {
                int e = k / EDGE_F, f = k - e * EDGE_F;
                EFf[f * 130 + e] = (e < c) ? __ldg(ef + (size_t)base * EDGE_F + k) : 0.f;
            }
            // ---- stage x gather into swizzled ull2 layout ----
            for (int t = tid; t < cpad * 4; t += 256) {
                int e = t >> 2, r = t & 3;
                float4 v = make_float4(0.f, 0.f, 0.f, 0.f);
                if (e < c) {
                    int src = __ldg(idxn + base + e);
                    v = __ldg((const float4*)x + (size_t)src * 4 + r);
                }
                int q = e >> 1, hh = e & 1;
                int s0 = (2 * r) ^ (q & 7), s1 = (2 * r + 1) ^ (q & 7);
                float* c0 = (float*)&SM->Xq[q][s0];
                float* c1 = (float*)&SM->Xq[q][s1];
                c0[hh]     = v.x;   // i=4r   (xa of pair 2r)
                c0[2 + hh] = v.y;   // i=4r+1 (xb of pair 2r)
                c1[hh]     = v.z;   // i=4r+2
                c1[2 + hh] = v.w;   // i=4r+3
            }
            __syncthreads();

            // ---- h pairs, q-blocked x4 (W1 row loaded once per 4 q) ----
            for (int t = tid; t < 512; t += 256) {
                int qb = t >> 5, jj = t & 31;
                ull h0 = SM->b1s[jj], h1 = h0, h2v = h0, h3 = h0;
                #pragma unroll
                for (int f = 0; f < EDGE_F; f++) {
                    ull w = SM->W1s[f][jj];
                    h0  = ffma2(SM->EFp[f][qb * 4 + 0], w, h0);
                    h1  = ffma2(SM->EFp[f][qb * 4 + 1], w, h1);
                    h2v = ffma2(SM->EFp[f][qb * 4 + 2], w, h2v);
                    h3  = ffma2(SM->EFp[f][qb * 4 + 3], w, h3);
                }
                float2 f0 = unpk(h0), f1 = unpk(h1), f2 = unpk(h2v), f3 = unpk(h3);
                SM->Hp[jj][qb * 4 + 0] = pk2(fmaxf(f0.x, 0.f), fmaxf(f0.y, 0.f));
                SM->Hp[jj][qb * 4 + 1] = pk2(fmaxf(f1.x, 0.f), fmaxf(f1.y, 0.f));
                SM->Hp[jj][qb * 4 + 2] = pk2(fmaxf(f2.x, 0.f), fmaxf(f2.y, 0.f));
                SM->Hp[jj][qb * 4 + 3] = pk2(fmaxf(f3.x, 0.f), fmaxf(f3.y, 0.f));
            }
            __syncthreads();

            const int cend = base + c;
            #pragma unroll 1
            for (int k = 0; k < NB; k++) {
                const int ak = SM->sb[k], bk = SM->sb[k + 1];
                int aL = ak - base; if (aL < 0) aL = 0;
                int bL = bk - base; if (bL > c) bL = c;
                if (bL > aL) {
                    const int qs = aL >> 1, qe = (bL - 1) >> 1;
                    const ull mlo = (aL & 1) ? 0xFFFFFFFF00000000ull : ~0ull;
                    const ull mhi = (bL & 1) ? 0x00000000FFFFFFFFull : ~0ull;
                    {
                        ull h2 = hrow[qs] & mlo;
                        if (qe == qs) h2 &= mhi;
                        ulonglong2 xv = SM->Xq[qs][p ^ (qs & 7)];
                        a0 = ffma2(h2, xv.x, a0);
                        a1 = ffma2(h2, xv.y, a1);
                    }
                    #pragma unroll 2
                    for (int q = qs + 1; q < qe; q++) {
                        ull h2 = hrow[q];
                        ulonglong2 xv = SM->Xq[q][p ^ (q & 7)];
                        a0 = ffma2(h2, xv.x, a0);
                        a1 = ffma2(h2, xv.y, a1);
                    }
                    if (qe > qs) {
                        ull h2 = hrow[qe] & mhi;
                        ulonglong2 xv = SM->Xq[qe][p ^ (qe & 7)];
                        a0 = ffma2(h2, xv.x, a0);
                        a1 = ffma2(h2, xv.y, a1);
                    }
                    if (tid < 16) {   // S accumulation (i = tid)
                        const int ip = tid >> 1, iw = tid & 1;
                        ull x2 = ((const ull*)&SM->Xq[qs][ip ^ (qs & 7)])[iw] & mlo;
                        if (qe == qs) x2 &= mhi;
                        aS = add2(aS, x2);
                        for (int q = qs + 1; q < qe; q++)
                            aS = add2(aS, ((const ull*)&SM->Xq[q][ip ^ (q & 7)])[iw]);
                        if (qe > qs)
                            aS = add2(aS, ((const ull*)&SM->Xq[qe][ip ^ (qe & 7)])[iw] & mhi);
                    }
                }
                if (bk > base && bk <= cend && bk > ak) {   // segment ends here
                    float2 fa = unpk(a0), fb = unpk(a1);
                    SM->Mbuf[k][tid] = pk2(fa.x + fa.y, fb.x + fb.y);
                    a0 = 0ull; a1 = 0ull;
                    if (tid < 16) {
                        float2 fs = unpk(aS);
                        ((float*)SM->Sb2)[k * 16 + tid] = fs.x + fs.y;
                        aS = 0ull;
                    }
                }
            }
            __syncthreads();
        }

        // ---- in-block GEMM, k-paired: LDS.128 + LDG.128 per 2 k ----
        const int half = tid >> 7;
        const int g = (tid >> 4) & 7;
        const int o = tid & 15;
        const ull* mrow = SM->Mbuf[g];
        const int k20 = half * 64;
        ull s = 0ull;
        #pragma unroll 8
        for (int k2 = k20; k2 < k20 + 64; k2++) {
            ulonglong2 m2 = *(const ulonglong2*)&mrow[2 * k2];
            ulonglong2 w2 = __ldg(&W2Q[k2][o]);
            s = ffma2(m2.x, w2.x, s);
            s = ffma2(m2.y, w2.y, s);
        }
        if (half) SM->red[g * 16 + o] = s;
        __syncthreads();
        if (!half) {
            s = add2(s, SM->red[g * 16 + o]);
            #pragma unroll
            for (int pp = 0; pp < 8; pp++)
                s = ffma2(SM->Sb2[g][pp], __ldg(&b2P[0][0] + pp * 16 + o), s);
            if (g < nn) {
                float2 f = unpk(s);
                float d = __ldg(degs + t0 + g);
                out[(t0 + g) * 16 + o] = (d > 0.f) ? (f.x + f.y) / d : 0.f;
            }
        }
    } else {
        // ================= node-0 slice blocks =================
        const int e0e = (int)__ldg(degs);   // node 0 owns edges [0, degs[0])
        ull a0 = 0ull, a1 = 0ull, aS = 0ull;
        __syncthreads();

        for (int base = bx * CH; base < e0e; base += EX * CH) {
            const int c = min(CH, e0e - base);
            const int cpad = (c + 1) & ~1;
            const int qn = cpad >> 1;

            for (int k = tid; k < cpad * EDGE_F; k += 256) {
                int e = k / EDGE_F, f = k - e * EDGE_F;
                EFf[f * 130 + e] = (e < c) ? __ldg(ef + (size_t)base * EDGE_F + k) : 0.f;
            }
            for (int t = tid; t < cpad * 4; t += 256) {
                int e = t >> 2, r = t & 3;
                float4 v = make_float4(0.f, 0.f, 0.f, 0.f);
                if (e < c) {
                    int src = __ldg(idxn + base + e);
                    v = __ldg((const float4*)x + (size_t)src * 4 + r);
                }
                int q = e >> 1, hh = e & 1;
                int s0 = (2 * r) ^ (q & 7), s1 = (2 * r + 1) ^ (q & 7);
                float* c0 = (float*)&SM->Xq[q][s0];
                float* c1 = (float*)&SM->Xq[q][s1];
                c0[hh]     = v.x;
                c0[2 + hh] = v.y;
                c1[hh]     = v.z;
                c1[2 + hh] = v.w;
            }
            __syncthreads();

            for (int t = tid; t < 512; t += 256) {
                int qb = t >> 5, jj = t & 31;
                ull h0 = SM->b1s[jj], h1 = h0, h2v = h0, h3 = h0;
                #pragma unroll
                for (int f = 0; f < EDGE_F; f++) {
                    ull w = SM->W1s[f][jj];
                    h0  = ffma2(SM->EFp[f][qb * 4 + 0], w, h0);
                    h1  = ffma2(SM->EFp[f][qb * 4 + 1], w, h1);
                    h2v = ffma2(SM->EFp[f][qb * 4 + 2], w, h2v);
                    h3  = ffma2(SM->EFp[f][qb * 4 + 3], w, h3);
                }
                float2 f0 = unpk(h0), f1 = unpk(h1), f2 = unpk(h2v), f3 = unpk(h3);
                SM->Hp[jj][qb * 4 + 0] = pk2(fmaxf(f0.x, 0.f), fmaxf(f0.y, 0.f));
                SM->Hp[jj][qb * 4 + 1] = pk2(fmaxf(f1.x, 0.f), fmaxf(f1.y, 0.f));
                SM->Hp[jj][qb * 4 + 2] = pk2(fmaxf(f2.x, 0.f), fmaxf(f2.y, 0.f));
                SM->Hp[jj][qb * 4 + 3] = pk2(fmaxf(f3.x, 0.f), fmaxf(f3.y, 0.f));
            }
            __syncthreads();

            #pragma unroll 2
            for (int q = 0; q < qn; q++) {      // pad edges have x = 0
                ull h2 = hrow[q];
                ulonglong2 xv = SM->Xq[q][p ^ (q & 7)];
                a0 = ffma2(h2, xv.x, a0);
                a1 = ffma2(h2, xv.y, a1);
            }
            if (tid < 16) {
                const int ip = tid >> 1, iw = tid & 1;
                for (int q = 0; q < qn; q++)
                    aS = add2(aS, ((const ull*)&SM->Xq[q][ip ^ (q & 7)])[iw]);
            }
            __syncthreads();
        }
        float2 fa = unpk(a0), fb = unpk(a1);
        Mg0x[bx][tid] = pk2(fa.x + fa.y, fb.x + fb.y);
        if (tid < 16) {
            float2 fs = unpk(aS);
            Sg0x[bx][tid] = fs.x + fs.y;
        }
    }
}

// ---------------------------------------------------------------------------
__global__ void __launch_bounds__(256)
node0_kernel(const float* __restrict__ degs, float* __restrict__ out)
{
    __shared__ float wred[8][16];
    __shared__ float ssum[16];
    int tid = threadIdx.x, lane = tid & 31, w = tid >> 5;

    ull m = Mg0x[0][tid];
    #pragma unroll
    for (int e2 = 1; e2 < EX; e2++) m = add2(m, Mg0x[e2][tid]);
    if (tid < 16) {
        float s = 0.f;
        #pragma unroll
        for (int e2 = 0; e2 < EX; e2++) s += Sg0x[e2][tid];
        ssum[tid] = s;
    }
    float po[16];
    #pragma unroll
    for (int o = 0; o < 16; o++) {
        ull wk = ((const ull*)&W2Q[tid >> 1][o])[tid & 1];
        ull t2 = ffma2(m, wk, 0ull);
        float2 f = unpk(t2);
        po[o] = f.x + f.y;
    }
    #pragma unroll
    for (int o = 0; o < 16; o++)
        #pragma unroll
        for (int off = 16; off; off >>= 1)
            po[o] += __shfl_down_sync(0xffffffffu, po[o], off);
    if (lane == 0)
        #pragma unroll
        for (int o = 0; o < 16; o++) wred[w][o] = po[o];
    __syncthreads();
    if (tid < 16) {
        float t = 0.f;
        #pragma unroll
        for (int w2 = 0; w2 < 8; w2++) t += wred[w2][tid];
        float s2 = 0.f;
        #pragma unroll
        for (int pp = 0; pp < 8; pp++) {
            ull q = ffma2(pk2(ssum[2 * pp], ssum[2 * pp + 1]), b2P[pp][tid], 0ull);
            float2 f = unpk(q);
            s2 += f.x + f.y;
        }
        float d = __ldg(degs);
        out[tid] = (d > 0.f) ? (t + s2) / d : 0.f;
    }
}

// ---------------------------------------------------------------------------
extern "C" void kernel_launch(void* const* d_in, const int* in_sizes, int n_in,
                              void* d_out, int out_size)
{
    const float* x    = (const float*)d_in[0];
    const float* ef   = (const float*)d_in[1];
    const float* W1   = (const float*)d_in[2];
    const float* b1   = (const float*)d_in[3];
    const float* W2   = (const float*)d_in[4];
    const float* b2   = (const float*)d_in[5];
    const int*   idxn = (const int*)d_in[6];
    const float* degs = (const float*)d_in[8];
    float* out = (float*)d_out;

    const int E = in_sizes[6];
    static int smem_set = 0;
    if (!smem_set) {
        cudaFuncSetAttribute(fused_kernel,
                             cudaFuncAttributeMaxDynamicSharedMemorySize,
                             (int)sizeof(SmemT));
        smem_set = 1;
    }

    pack_kernel<<<1, 256>>>(W2, b2);
    scan1_kernel<<<SCAN_NB, SCAN_B>>>(degs);
    scan2_kernel<<<1, 128>>>();
    fused_kernel<<<EX + NBLK, 256, sizeof(SmemT)>>>(x, ef, W1, b1, idxn, degs, out, E);
    node0_kernel<<<1, 256>>>(degs, out);
}

// round 8
// speedup vs baseline: 1.4411x; 1.1766x over previous
#include <cuda_runtime.h>

#define N_NODES 50000
#define EDGE_F  13
#define HID     32
#define NB      8            // nodes per main block (deg<=32 -> <=256 edges)
#define CH      128          // edges per staging chunk
#define PAIRS   64           // CH/2
#define EFS     66           // EFp/Hp row stride in ull (16B-aligned, even)
#define EX      16           // node-0 slice blocks (first in grid)
#define NBLK    ((N_NODES + NB - 1) / NB)   // 6250
#define SCAN_B  512
#define SCAN_NB ((N_NODES + SCAN_B - 1) / SCAN_B)   // 98

typedef unsigned long long ull;

__device__ ulonglong2 W2Q[128][16];   // k-paired packed W2 (8 KB, L1-hot)
__device__ ull        b2P[8][16];
__device__ ull        Mg0x[EX][256];
__device__ float      Sg0x[EX][16];
__device__ int        StartsG[N_NODES];
__device__ int        PsumG[128];
__device__ int        OffG[128];

// ---- packed fp32x2 helpers (sm_103a FFMA2, PTX-only) ----
__device__ __forceinline__ ull pk2(float a, float b) {
    ull r; asm("mov.b64 %0, {%1,%2};" : "=l"(r) : "f"(a), "f"(b)); return r;
}
__device__ __forceinline__ ull ffma2(ull a, ull b, ull c) {
    ull d; asm("fma.rn.f32x2 %0, %1, %2, %3;" : "=l"(d) : "l"(a), "l"(b), "l"(c)); return d;
}
__device__ __forceinline__ ull add2(ull a, ull b) {
    ull d; asm("add.rn.f32x2 %0, %1, %2;" : "=l"(d) : "l"(a), "l"(b)); return d;
}
__device__ __forceinline__ float2 unpk(ull a) {
    float2 f; asm("mov.b64 {%0,%1}, %2;" : "=f"(f.x), "=f"(f.y) : "l"(a)); return f;
}

// ---------------------------------------------------------------------------
__global__ void pack_kernel(const float* __restrict__ W2, const float* __restrict__ b2)
{
    int tid = threadIdx.x;
    for (int t = tid; t < 128 * 16; t += 256) {
        int k2 = t >> 4, o = t & 15;
        int k0 = 2 * k2, k1 = 2 * k2 + 1;
        int j0 = k0 >> 3, p0 = k0 & 7;
        int j1 = k1 >> 3, p1 = k1 & 7;
        ulonglong2 v;
        v.x = pk2(__ldg(W2 + j0 * 256 + 2 * p0 * 16 + o),
                  __ldg(W2 + j0 * 256 + (2 * p0 + 1) * 16 + o));
        v.y = pk2(__ldg(W2 + j1 * 256 + 2 * p1 * 16 + o),
                  __ldg(W2 + j1 * 256 + (2 * p1 + 1) * 16 + o));
        W2Q[k2][o] = v;
    }
    if (tid < 128) {
        int pp = tid >> 4, o = tid & 15;
        b2P[pp][o] = pk2(__ldg(b2 + 2 * pp * 16 + o),
                         __ldg(b2 + (2 * pp + 1) * 16 + o));
    }
}

__global__ void scan1_kernel(const float* __restrict__ degs)
{
    __shared__ int s[SCAN_B];
    int b = blockIdx.x, t = threadIdx.x, n = b * SCAN_B + t;
    int d = (n < N_NODES) ? (int)degs[n] : 0;
    s[t] = d;
    for (int off = 1; off < SCAN_B; off <<= 1) {
        __syncthreads();
        int v = (t >= off) ? s[t - off] : 0;
        __syncthreads();
        s[t] += v;
    }
    if (n < N_NODES) StartsG[n] = s[t] - d;     // exclusive
    if (t == SCAN_B - 1) PsumG[b] = s[t];
}

__global__ void scan2_kernel()
{
    __shared__ int s[128];
    int t = threadIdx.x;
    s[t] = (t < SCAN_NB) ? PsumG[t] : 0;
    __syncthreads();
    if (t == 0) {
        int acc = 0;
        for (int i = 0; i < SCAN_NB; i++) { int v = s[i]; s[i] = acc; acc += v; }
    }
    __syncthreads();
    if (t < SCAN_NB) OffG[t] = s[t];
}

// ---------------------------------------------------------------------------
struct __align__(16) SmemT {
    ulonglong2 Xq[PAIRS][8];      // 8.0 KB  x pairs, slot = p ^ (q&7)
    ull Mbuf[NB][260];            // 16.6 KB (16B-aligned rows)
    ull Hp[HID][EFS];             // 16.9 KB packed {h(2q), h(2q+1)}; GEMM partials alias
    ull EFp[EDGE_F][EFS];         // 6.9 KB
    ull W1s[EDGE_F][HID];         // 3.3 KB packed {w,w}
    ull b1s[HID];
    ull Sb2[NB][8];
    int sb[NB + 4];
};                                // ~52.5 KB -> 4 blocks/SM

// single masked pair update
#define ACC_ONE(Q, MASK)                                           \
    { ull h2 = hrow[Q] & (MASK);                                   \
      ulonglong2 xv = SM->Xq[Q][p ^ ((Q) & 7)];                    \
      a0 = ffma2(h2, xv.x, a0); a1 = ffma2(h2, xv.y, a1); }
// unmasked pair update
#define ACC_FULL(Q)                                                \
    { ull h2 = hrow[Q];                                            \
      ulonglong2 xv = SM->Xq[Q][p ^ ((Q) & 7)];                    \
      a0 = ffma2(h2, xv.x, a0); a1 = ffma2(h2, xv.y, a1); }
// two pairs (Q even): one LDS.128 on hrow
#define ACC_TWO(Q)                                                 \
    { ulonglong2 h4 = *(const ulonglong2*)&hrow[Q];                \
      ulonglong2 xv0 = SM->Xq[Q][p ^ ((Q) & 7)];                   \
      ulonglong2 xv1 = SM->Xq[(Q) + 1][p ^ (((Q) + 1) & 7)];       \
      a0 = ffma2(h4.x, xv0.x, a0); a1 = ffma2(h4.x, xv0.y, a1);    \
      a0 = ffma2(h4.y, xv1.x, a0); a1 = ffma2(h4.y, xv1.y, a1); }

__global__ void __launch_bounds__(256, 4)
fused_kernel(const float* __restrict__ x,
             const float* __restrict__ ef,
             const float* __restrict__ W1,
             const float* __restrict__ b1,
             const int*   __restrict__ idxn,
             const float* __restrict__ degs,
             float* __restrict__ out,
             int E)
{
    extern __shared__ char smem_raw[];
    SmemT* SM = (SmemT*)smem_raw;
    const int tid = threadIdx.x;
    const int bx  = blockIdx.x;
    const int j = tid >> 3, p = tid & 7;

    for (int t = tid; t < EDGE_F * HID; t += 256) {
        float w = __ldg(W1 + t);
        SM->W1s[t / HID][t % HID] = pk2(w, w);
    }
    if (tid < HID) { float bb = __ldg(b1 + tid); SM->b1s[tid] = pk2(bb, bb); }

    float* EFf = (float*)SM->EFp;       // row stride 2*EFS floats
    const ull* hrow = SM->Hp[j];

    if (bx >= EX) {
        // ================= main blocks: 8 nodes =================
        const int mb = bx - EX;
        const int t0 = (mb == 0) ? 1 : mb * NB;     // node 0 excluded
        int t1 = mb * NB + NB; if (t1 > N_NODES) t1 = N_NODES;
        const int nn = t1 - t0;

        if (tid <= NB) {
            int target = t0 + tid; if (target > t1) target = t1;
            SM->sb[tid] = (target >= N_NODES) ? E
                          : (StartsG[target] + OffG[target >> 9]);
        }
        __syncthreads();

        const int es = SM->sb[0];
        const int ee = SM->sb[NB];
        ull a0 = 0ull, a1 = 0ull, aS = 0ull;

        for (int base = es; base < ee; base += CH) {
            const int c = min(CH, ee - base);
            const int cpad = (c + 1) & ~1;

            // ---- stage ef (zero-padded to cpad) ----
            for (int k = tid; k < cpad * EDGE_F; k += 256) {
                int e = k / EDGE_F, f = k - e * EDGE_F;
                EFf[f * (2 * EFS) + e] =
                    (e < c) ? __ldg(ef + (size_t)base * EDGE_F + k) : 0.f;
            }
            // ---- stage x gather into swizzled ull2 layout ----
            for (int t = tid; t < cpad * 4; t += 256) {
                int e = t >> 2, r = t & 3;
                float4 v = make_float4(0.f, 0.f, 0.f, 0.f);
                if (e < c) {
                    int src = __ldg(idxn + base + e);
                    v = __ldg((const float4*)x + (size_t)src * 4 + r);
                }
                int q = e >> 1, hh = e & 1;
                int s0 = (2 * r) ^ (q & 7), s1 = (2 * r + 1) ^ (q & 7);
                float* c0 = (float*)&SM->Xq[q][s0];
                float* c1 = (float*)&SM->Xq[q][s1];
                c0[hh]     = v.x;
                c0[2 + hh] = v.y;
                c1[hh]     = v.z;
                c1[2 + hh] = v.w;
            }
            __syncthreads();

            // ---- h pairs: paired LDS.128 on EF, STS.128 on Hp ----
            for (int t = tid; t < 512; t += 256) {
                int qb = t >> 5, jj = t & 31;
                ull h0 = SM->b1s[jj], h1 = h0, h2v = h0, h3 = h0;
                #pragma unroll
                for (int f = 0; f < EDGE_F; f++) {
                    ull w = SM->W1s[f][jj];
                    ulonglong2 eA = *(const ulonglong2*)&SM->EFp[f][qb * 4];
                    ulonglong2 eB = *(const ulonglong2*)&SM->EFp[f][qb * 4 + 2];
                    h0  = ffma2(eA.x, w, h0);
                    h1  = ffma2(eA.y, w, h1);
                    h2v = ffma2(eB.x, w, h2v);
                    h3  = ffma2(eB.y, w, h3);
                }
                float2 f0 = unpk(h0), f1 = unpk(h1), f2 = unpk(h2v), f3 = unpk(h3);
                ulonglong2 oA, oB;
                oA.x = pk2(fmaxf(f0.x, 0.f), fmaxf(f0.y, 0.f));
                oA.y = pk2(fmaxf(f1.x, 0.f), fmaxf(f1.y, 0.f));
                oB.x = pk2(fmaxf(f2.x, 0.f), fmaxf(f2.y, 0.f));
                oB.y = pk2(fmaxf(f3.x, 0.f), fmaxf(f3.y, 0.f));
                *(ulonglong2*)&SM->Hp[jj][qb * 4]     = oA;
                *(ulonglong2*)&SM->Hp[jj][qb * 4 + 2] = oB;
            }
            __syncthreads();

            const int cend = base + c;
            #pragma unroll 1
            for (int k = 0; k < NB; k++) {
                const int ak = SM->sb[k], bk = SM->sb[k + 1];
                int aL = ak - base; if (aL < 0) aL = 0;
                int bL = bk - base; if (bL > c) bL = c;
                if (bL > aL) {
                    const int qs = aL >> 1, qe = (bL - 1) >> 1;
                    const ull mlo = (aL & 1) ? 0xFFFFFFFF00000000ull : ~0ull;
                    const ull mhi = (bL & 1) ? 0x00000000FFFFFFFFull : ~0ull;
                    if (qe == qs) {
                        ACC_ONE(qs, mlo & mhi);
                    } else {
                        ACC_ONE(qs, mlo);
                        int q = qs + 1;
                        if ((q & 1) && q < qe) { ACC_FULL(q); q++; }
                        #pragma unroll 2
                        for (; q + 1 < qe; q += 2) ACC_TWO(q);
                        if (q < qe) { ACC_FULL(q); q++; }
                        ACC_ONE(qe, mhi);
                    }
                    if (tid < 16) {   // S accumulation (i = tid)
                        const int ip = tid >> 1, iw = tid & 1;
                        ull x2 = ((const ull*)&SM->Xq[qs][ip ^ (qs & 7)])[iw] & mlo;
                        if (qe == qs) x2 &= mhi;
                        aS = add2(aS, x2);
                        for (int q = qs + 1; q < qe; q++)
                            aS = add2(aS, ((const ull*)&SM->Xq[q][ip ^ (q & 7)])[iw]);
                        if (qe > qs)
                            aS = add2(aS, ((const ull*)&SM->Xq[qe][ip ^ (qe & 7)])[iw] & mhi);
                    }
                }
                if (bk > base && bk <= cend && bk > ak) {   // segment ends here
                    float2 fa = unpk(a0), fb = unpk(a1);
                    SM->Mbuf[k][tid] = pk2(fa.x + fa.y, fb.x + fb.y);
                    a0 = 0ull; a1 = 0ull;
                    if (tid < 16) {
                        float2 fs = unpk(aS);
                        ((float*)SM->Sb2)[k * 16 + tid] = fs.x + fs.y;
                        aS = 0ull;
                    }
                }
            }
            __syncthreads();
        }

        // ---- GEMM: 8-way k-split, each warp covers all 8 nodes ----
        {
            const int w = tid >> 5, lane = tid & 31;
            const int o = lane & 15, gh = lane >> 4;     // gh: node half
            ull s0g = 0ull, s1g = 0ull, s2g = 0ull, s3g = 0ull;
            const int k2b = w * 16;
            #pragma unroll 4
            for (int k2 = k2b; k2 < k2b + 16; k2++) {
                ulonglong2 w2 = __ldg(&W2Q[k2][o]);
                ulonglong2 m0 = *(const ulonglong2*)&SM->Mbuf[gh * 4 + 0][2 * k2];
                ulonglong2 m1 = *(const ulonglong2*)&SM->Mbuf[gh * 4 + 1][2 * k2];
                ulonglong2 m2 = *(const ulonglong2*)&SM->Mbuf[gh * 4 + 2][2 * k2];
                ulonglong2 m3 = *(const ulonglong2*)&SM->Mbuf[gh * 4 + 3][2 * k2];
                s0g = ffma2(m0.x, w2.x, s0g); s0g = ffma2(m0.y, w2.y, s0g);
                s1g = ffma2(m1.x, w2.x, s1g); s1g = ffma2(m1.y, w2.y, s1g);
                s2g = ffma2(m2.x, w2.x, s2g); s2g = ffma2(m2.y, w2.y, s2g);
                s3g = ffma2(m3.x, w2.x, s3g); s3g = ffma2(m3.y, w2.y, s3g);
            }
            ull* Gred = &SM->Hp[0][0];       // Hp dead after last chunk
            Gred[w * 128 + (gh * 4 + 0) * 16 + o] = s0g;
            Gred[w * 128 + (gh * 4 + 1) * 16 + o] = s1g;
            Gred[w * 128 + (gh * 4 + 2) * 16 + o] = s2g;
            Gred[w * 128 + (gh * 4 + 3) * 16 + o] = s3g;
        }
        __syncthreads();
        if (tid < 128) {
            const int g = tid >> 4, o = tid & 15;
            const ull* Gred = &SM->Hp[0][0];
            ull s = Gred[g * 16 + o];
            #pragma unroll
            for (int w = 1; w < 8; w++) s = add2(s, Gred[w * 128 + g * 16 + o]);
            #pragma unroll
            for (int pp = 0; pp < 8; pp++)
                s = ffma2(SM->Sb2[g][pp], __ldg(&b2P[0][0] + pp * 16 + o), s);
            if (g < nn) {
                float2 f = unpk(s);
                float d = __ldg(degs + t0 + g);
                out[(t0 + g) * 16 + o] = (d > 0.f) ? (f.x + f.y) / d : 0.f;
            }
        }
    } else {
        // ================= node-0 slice blocks =================
        const int e0e = (int)__ldg(degs);   // node 0 owns edges [0, degs[0])
        ull a0 = 0ull, a1 = 0ull, aS = 0ull;
        __syncthreads();

        for (int base = bx * CH; base < e0e; base += EX * CH) {
            const int c = min(CH, e0e - base);
            const int cpad = (c + 1) & ~1;
            const int qn = cpad >> 1;

            for (int k = tid; k < cpad * EDGE_F; k += 256) {
                int e = k / EDGE_F, f = k - e * EDGE_F;
                EFf[f * (2 * EFS) + e] =
                    (e < c) ? __ldg(ef + (size_t)base * EDGE_F + k) : 0.f;
            }
            for (int t = tid; t < cpad * 4; t += 256) {
                int e = t >> 2, r = t & 3;
                float4 v = make_float4(0.f, 0.f, 0.f, 0.f);
                if (e < c) {
                    int src = __ldg(idxn + base + e);
                    v = __ldg((const float4*)x + (size_t)src * 4 + r);
                }
                int q = e >> 1, hh = e & 1;
                int s0 = (2 * r) ^ (q & 7), s1 = (2 * r + 1) ^ (q & 7);
                float* c0 = (float*)&SM->Xq[q][s0];
                float* c1 = (float*)&SM->Xq[q][s1];
                c0[hh]     = v.x;
                c0[2 + hh] = v.y;
                c1[hh]     = v.z;
                c1[2 + hh] = v.w;
            }
            __syncthreads();

            for (int t = tid; t < 512; t += 256) {
                int qb = t >> 5, jj = t & 31;
                ull h0 = SM->b1s[jj], h1 = h0, h2v = h0, h3 = h0;
                #pragma unroll
                for (int f = 0; f < EDGE_F; f++) {
                    ull w = SM->W1s[f][jj];
                    ulonglong2 eA = *(const ulonglong2*)&SM->EFp[f][qb * 4];
                    ulonglong2 eB = *(const ulonglong2*)&SM->EFp[f][qb * 4 + 2];
                    h0  = ffma2(eA.x, w, h0);
                    h1  = ffma2(eA.y, w, h1);
                    h2v = ffma2(eB.x, w, h2v);
                    h3  = ffma2(eB.y, w, h3);
                }
                float2 f0 = unpk(h0), f1 = unpk(h1), f2 = unpk(h2v), f3 = unpk(h3);
                ulonglong2 oA, oB;
                oA.x = pk2(fmaxf(f0.x, 0.f), fmaxf(f0.y, 0.f));
                oA.y = pk2(fmaxf(f1.x, 0.f), fmaxf(f1.y, 0.f));
                oB.x = pk2(fmaxf(f2.x, 0.f), fmaxf(f2.y, 0.f));
                oB.y = pk2(fmaxf(f3.x, 0.f), fmaxf(f3.y, 0.f));
                *(ulonglong2*)&SM->Hp[jj][qb * 4]     = oA;
                *(ulonglong2*)&SM->Hp[jj][qb * 4 + 2] = oB;
            }
            __syncthreads();

            {
                int q = 0;
                #pragma unroll 2
                for (; q + 1 < qn; q += 2) ACC_TWO(q);
                if (q < qn) ACC_FULL(q);
            }
            if (tid < 16) {
                const int ip = tid >> 1, iw = tid & 1;
                for (int q = 0; q < qn; q++)
                    aS = add2(aS, ((const ull*)&SM->Xq[q][ip ^ (q & 7)])[iw]);
            }
            __syncthreads();
        }
        float2 fa = unpk(a0), fb = unpk(a1);
        Mg0x[bx][tid] = pk2(fa.x + fa.y, fb.x + fb.y);
        if (tid < 16) {
            float2 fs = unpk(aS);
            Sg0x[bx][tid] = fs.x + fs.y;
        }
    }
}

// ---------------------------------------------------------------------------
__global__ void __launch_bounds__(256)
node0_kernel(const float* __restrict__ degs, float* __restrict__ out)
{
    __shared__ float wred[8][16];
    __shared__ float ssum[16];
    int tid = threadIdx.x, lane = tid & 31, w = tid >> 5;

    ull m = Mg0x[0][tid];
    #pragma unroll
    for (int e2 = 1; e2 < EX; e2++) m = add2(m, Mg0x[e2][tid]);
    if (tid < 16) {
        float s = 0.f;
        #pragma unroll
        for (int e2 = 0; e2 < EX; e2++) s += Sg0x[e2][tid];
        ssum[tid] = s;
    }
    float po[16];
    #pragma unroll
    for (int o = 0; o < 16; o++) {
        ull wk = ((const ull*)&W2Q[tid >> 1][o])[tid & 1];
        ull t2 = ffma2(m, wk, 0ull);
        float2 f = unpk(t2);
        po[o] = f.x + f.y;
    }
    #pragma unroll
    for (int o = 0; o < 16; o++)
        #pragma unroll
        for (int off = 16; off; off >>= 1)
            po[o] += __shfl_down_sync(0xffffffffu, po[o], off);
    if (lane == 0)
        #pragma unroll
        for (int o = 0; o < 16; o++) wred[w][o] = po[o];
    __syncthreads();
    if (tid < 16) {
        float t = 0.f;
        #pragma unroll
        for (int w2 = 0; w2 < 8; w2++) t += wred[w2][tid];
        float s2 = 0.f;
        #pragma unroll
        for (int pp = 0; pp < 8; pp++) {
            ull q = ffma2(pk2(ssum[2 * pp], ssum[2 * pp + 1]), b2P[pp][tid], 0ull);
            float2 f = unpk(q);
            s2 += f.x + f.y;
        }
        float d = __ldg(degs);
        out[tid] = (d > 0.f) ? (t + s2) / d : 0.f;
    }
}

// ---------------------------------------------------------------------------
extern "C" void kernel_launch(void* const* d_in, const int* in_sizes, int n_in,
                              void* d_out, int out_size)
{
    const float* x    = (const float*)d_in[0];
    const float* ef   = (const float*)d_in[1];
    const float* W1   = (const float*)d_in[2];
    const float* b1   = (const float*)d_in[3];
    const float* W2   = (const float*)d_in[4];
    const float* b2   = (const float*)d_in[5];
    const int*   idxn = (const int*)d_in[6];
    const float* degs = (const float*)d_in[8];
    float* out = (float*)d_out;

    const int E = in_sizes[6];
    static int smem_set = 0;
    if (!smem_set) {
        cudaFuncSetAttribute(fused_kernel,
                             cudaFuncAttributeMaxDynamicSharedMemorySize,
                             (int)sizeof(SmemT));
        smem_set = 1;
    }

    pack_kernel<<<1, 256>>>(W2, b2);
    scan1_kernel<<<SCAN_NB, SCAN_B>>>(degs);
    scan2_kernel<<<1, 128>>>();
    fused_kernel<<<EX + NBLK, 256, sizeof(SmemT)>>>(x, ef, W1, b1, idxn, degs, out, E);
    node0_kernel<<<1, 256>>>(degs, out);
}